// round 8
// baseline (speedup 1.0000x reference)
#include <cuda_runtime.h>

// PMLoss: PoseCNN point-matching loss. Two kernels:
//  pm_setup : per-ROI argmax/quats, pre-rotated packed target tables (GMEM),
//             deterministic heavy-first unit list.
//  pm_main  : one block per (ROI, p-chunk) unit; symmetric units scan the
//             L1-resident packed table with packed f32x2 FMA.

#define NB        128
#define NC        22
#define NP        1024
#define NPAIR     (NP / 2)
#define NCHUNK    8
#define NTHREADS  128                  // == NP / NCHUNK : one p per thread
#define NBLOCKS   (NB * NCHUNK)
#define BIGF      3.402823e38f

#define FXSCALE   1099511627776.0      // 2^40 fixed-point scale

// Packed target tables: per ROI, NPAIR entries of
//   xy = { (-2x0,-2x1), (-2y0,-2y1) },  zw = { (-2z0,-2z1), (n0,n1) }
__device__ ulonglong2 g_xy[NB][NPAIR];   // 1 MB
__device__ ulonglong2 g_zw[NB][NPAIR];   // 1 MB
__device__ float g_Rp[NB][9];
__device__ float g_Rt[NB][9];
__device__ int   g_cls[NB];
__device__ int   g_hvy[NB];
__device__ int   g_units[NBLOCKS];       // heavy-first (b*NCHUNK+chunk) ids

__device__ unsigned long long g_acc;     // zero at load; last block resets
__device__ unsigned int       g_count;   // zero at load; last block resets

__device__ __forceinline__ unsigned long long pack2(float lo, float hi) {
    unsigned long long r;
    asm("mov.b64 %0, {%1, %2};" : "=l"(r) : "f"(lo), "f"(hi));
    return r;
}
__device__ __forceinline__ void unpack2(unsigned long long v, float& lo, float& hi) {
    asm("mov.b64 {%0, %1}, %2;" : "=f"(lo), "=f"(hi) : "l"(v));
}
// Packed dual fp32 FMA (FFMA2) — only reachable via PTX fma.rn.f32x2.
__device__ __forceinline__ unsigned long long fma2(
    unsigned long long a, unsigned long long b, unsigned long long c) {
    unsigned long long d;
    asm("fma.rn.f32x2 %0, %1, %2, %3;" : "=l"(d) : "l"(a), "l"(b), "l"(c));
    return d;
}

__device__ __forceinline__ float warp_reduce_sum(float v) {
    v += __shfl_xor_sync(0xffffffffu, v, 16);
    v += __shfl_xor_sync(0xffffffffu, v, 8);
    v += __shfl_xor_sync(0xffffffffu, v, 4);
    v += __shfl_xor_sync(0xffffffffu, v, 2);
    v += __shfl_xor_sync(0xffffffffu, v, 1);
    return v;
}

__device__ __forceinline__ int roi_argmax(const float* __restrict__ wgt, int r) {
    const float* w = wgt + r * 4 * NC;
    int cls = 0; float best = w[0];
    #pragma unroll
    for (int c = 1; c < NC; c++) {
        float v = w[4 * c];
        if (v > best) { best = v; cls = c; }
    }
    return cls;
}

__device__ __forceinline__ void quat_to_R(float qw, float qx, float qy, float qz,
                                          float* R) {
    R[0] = 1.f - 2.f*(qy*qy + qz*qz); R[1] = 2.f*(qx*qy - qw*qz); R[2] = 2.f*(qx*qz + qw*qy);
    R[3] = 2.f*(qx*qy + qw*qz); R[4] = 1.f - 2.f*(qx*qx + qz*qz); R[5] = 2.f*(qy*qz - qw*qx);
    R[6] = 2.f*(qx*qz - qw*qy); R[7] = 2.f*(qy*qz + qw*qx); R[8] = 1.f - 2.f*(qx*qx + qy*qy);
}

// ── Kernel A: per-ROI setup + heavy-first unit list + packed tables ──
__global__ __launch_bounds__(NTHREADS) void pm_setup(
    const float* __restrict__ pred, const float* __restrict__ tgt,
    const float* __restrict__ wgt,  const float* __restrict__ points,
    const float* __restrict__ sym)
{
    const int b   = blockIdx.x;          // one block per ROI
    const int tid = threadIdx.x;

    __shared__ int   s_flag[NB];         // heavy flags for ALL ROIs
    __shared__ float s_Rt[9];
    __shared__ int   s_cls;
    __shared__ int   s_heavy;

    // Thread t classifies ROI t (NTHREADS == NB)
    {
        int c = roi_argmax(wgt, tid);
        s_flag[tid] = (sym[c] > 0.f) ? 1 : 0;
    }

    if (tid == 0) {
        int cls = roi_argmax(wgt, b);
        s_cls = cls;
        g_cls[b] = cls;

        const float* qp = pred + b * 4 * NC + 4 * cls;
        float qw = qp[0], qx = qp[1], qy = qp[2], qz = qp[3];
        float inv = rsqrtf(qw*qw + qx*qx + qy*qy + qz*qz);
        float Rp[9];
        quat_to_R(qw*inv, qx*inv, qy*inv, qz*inv, Rp);
        #pragma unroll
        for (int i = 0; i < 9; i++) g_Rp[b][i] = Rp[i];

        const float* qt = tgt + b * 4 * NC + 4 * cls;
        float Rt[9];
        quat_to_R(qt[0], qt[1], qt[2], qt[3], Rt);
        #pragma unroll
        for (int i = 0; i < 9; i++) { g_Rt[b][i] = Rt[i]; s_Rt[i] = Rt[i]; }
    }
    __syncthreads();

    const int heavy = s_flag[b];
    if (tid == 0) { g_hvy[b] = heavy; s_heavy = heavy; }

    // Deterministic heavy-first unit placement (exact prefix sums)
    if (tid < NCHUNK) {
        int H = 0, hrank = 0;
        #pragma unroll
        for (int r = 0; r < NB; r++) {
            H += s_flag[r];
            if (r < b) hrank += s_flag[r];
        }
        int base = heavy ? NCHUNK * hrank
                         : NCHUNK * (H + (b - hrank));
        g_units[base + tid] = b * NCHUNK + tid;
    }
    __syncthreads();

    // Heavy ROIs: rotate + pack target table to GMEM
    if (s_heavy) {
        const float r0 = s_Rt[0], r1 = s_Rt[1], r2 = s_Rt[2];
        const float r3 = s_Rt[3], r4 = s_Rt[4], r5 = s_Rt[5];
        const float r6 = s_Rt[6], r7 = s_Rt[7], r8 = s_Rt[8];
        const float* pts = points + (size_t)s_cls * NP * 3;
        for (int i = tid; i < NPAIR; i += NTHREADS) {
            int q0 = 2 * i;
            float x0 = pts[3*q0+0], y0 = pts[3*q0+1], z0 = pts[3*q0+2];
            float x1 = pts[3*q0+3], y1 = pts[3*q0+4], z1 = pts[3*q0+5];
            float tx0 = r0*x0 + r1*y0 + r2*z0, tx1 = r0*x1 + r1*y1 + r2*z1;
            float ty0 = r3*x0 + r4*y0 + r5*z0, ty1 = r3*x1 + r4*y1 + r5*z1;
            float tz0 = r6*x0 + r7*y0 + r8*z0, tz1 = r6*x1 + r7*y1 + r8*z1;
            float n0 = tx0*tx0 + ty0*ty0 + tz0*tz0;
            float n1 = tx1*tx1 + ty1*ty1 + tz1*tz1;
            ulonglong2 xy, zw;
            xy.x = pack2(-2.f*tx0, -2.f*tx1);
            xy.y = pack2(-2.f*ty0, -2.f*ty1);
            zw.x = pack2(-2.f*tz0, -2.f*tz1);
            zw.y = pack2(n0, n1);
            g_xy[b][i] = xy;
            g_zw[b][i] = zw;
        }
    }
}

// ── Kernel B: one block per unit, heavy units first ──
__global__ __launch_bounds__(NTHREADS, 4) void pm_main(
    const float* __restrict__ points, float* __restrict__ out)
{
    const int tid  = threadIdx.x;
    const int unit = g_units[blockIdx.x];
    const int b     = unit >> 3;          // NCHUNK == 8
    const int chunk = unit & (NCHUNK - 1);

    __shared__ float s_warp[NTHREADS / 32];

    const int cls   = g_cls[b];
    const int heavy = g_hvy[b];
    const float* pts = points + (size_t)cls * NP * 3;

    // Own predicted-rotated point
    const int p = chunk * NTHREADS + tid;
    const float px = pts[3*p], py = pts[3*p + 1], pz = pts[3*p + 2];
    float ppx, ppy, ppz;
    {
        const float* Rp = g_Rp[b];
        float r0 = Rp[0], r1 = Rp[1], r2 = Rp[2];
        float r3 = Rp[3], r4 = Rp[4], r5 = Rp[5];
        float r6 = Rp[6], r7 = Rp[7], r8 = Rp[8];
        ppx = r0*px + r1*py + r2*pz;
        ppy = r3*px + r4*py + r5*pz;
        ppz = r6*px + r7*py + r8*pz;
    }
    const float cp = ppx*ppx + ppy*ppy + ppz*ppz;

    float acc;
    if (heavy) {
        // min_q |pp - pt_q|^2 = cp + min_q(n_q - 2 pp.pt_q)
        // Table streamed via LDG (broadcast, L1-resident), packed FMA.
        const ulonglong2* __restrict__ xp = g_xy[b];
        const ulonglong2* __restrict__ zp = g_zw[b];
        const unsigned long long px2 = pack2(ppx, ppx);
        const unsigned long long py2 = pack2(ppy, ppy);
        const unsigned long long pz2 = pack2(ppz, ppz);
        float m0 = BIGF, m1 = BIGF, m2 = BIGF, m3 = BIGF;
        float m4 = BIGF, m5 = BIGF, m6 = BIGF, m7 = BIGF;

        #pragma unroll 1
        for (int i = 0; i < NPAIR; i += 8) {
            ulonglong2 x0 = xp[i+0], z0 = zp[i+0];
            ulonglong2 x1 = xp[i+1], z1 = zp[i+1];
            ulonglong2 x2 = xp[i+2], z2 = zp[i+2];
            ulonglong2 x3 = xp[i+3], z3 = zp[i+3];
            ulonglong2 x4 = xp[i+4], z4 = zp[i+4];
            ulonglong2 x5 = xp[i+5], z5 = zp[i+5];
            ulonglong2 x6 = xp[i+6], z6 = zp[i+6];
            ulonglong2 x7 = xp[i+7], z7 = zp[i+7];

            unsigned long long v0 = fma2(pz2, z0.x, fma2(py2, x0.y, fma2(px2, x0.x, z0.y)));
            unsigned long long v1 = fma2(pz2, z1.x, fma2(py2, x1.y, fma2(px2, x1.x, z1.y)));
            unsigned long long v2 = fma2(pz2, z2.x, fma2(py2, x2.y, fma2(px2, x2.x, z2.y)));
            unsigned long long v3 = fma2(pz2, z3.x, fma2(py2, x3.y, fma2(px2, x3.x, z3.y)));
            unsigned long long v4 = fma2(pz2, z4.x, fma2(py2, x4.y, fma2(px2, x4.x, z4.y)));
            unsigned long long v5 = fma2(pz2, z5.x, fma2(py2, x5.y, fma2(px2, x5.x, z5.y)));
            unsigned long long v6 = fma2(pz2, z6.x, fma2(py2, x6.y, fma2(px2, x6.x, z6.y)));
            unsigned long long v7 = fma2(pz2, z7.x, fma2(py2, x7.y, fma2(px2, x7.x, z7.y)));

            float a, bf;
            unpack2(v0, a, bf); m0 = fminf(m0, a); m1 = fminf(m1, bf);
            unpack2(v1, a, bf); m2 = fminf(m2, a); m3 = fminf(m3, bf);
            unpack2(v2, a, bf); m4 = fminf(m4, a); m5 = fminf(m5, bf);
            unpack2(v3, a, bf); m6 = fminf(m6, a); m7 = fminf(m7, bf);
            unpack2(v4, a, bf); m0 = fminf(m0, a); m1 = fminf(m1, bf);
            unpack2(v5, a, bf); m2 = fminf(m2, a); m3 = fminf(m3, bf);
            unpack2(v6, a, bf); m4 = fminf(m4, a); m5 = fminf(m5, bf);
            unpack2(v7, a, bf); m6 = fminf(m6, a); m7 = fminf(m7, bf);
        }
        acc = cp + fminf(fminf(fminf(m0, m1), fminf(m2, m3)),
                         fminf(fminf(m4, m5), fminf(m6, m7)));
    } else {
        // Non-symmetric: rotate own point by Rt; |pp - pt|^2
        const float* Rt = g_Rt[b];
        float r0 = Rt[0], r1 = Rt[1], r2 = Rt[2];
        float r3 = Rt[3], r4 = Rt[4], r5 = Rt[5];
        float r6 = Rt[6], r7 = Rt[7], r8 = Rt[8];
        float tx = r0*px + r1*py + r2*pz;
        float ty = r3*px + r4*py + r5*pz;
        float tz = r6*px + r7*py + r8*pz;
        float dx = ppx - tx, dy = ppy - ty, dz = ppz - tz;
        acc = dx*dx + dy*dy + dz*dz;
        (void)cp;
    }

    // Block reduction
    float s = warp_reduce_sum(acc);
    if ((tid & 31) == 0) s_warp[tid >> 5] = s;
    __syncthreads();
    if (tid == 0) {
        float v = s_warp[0];
        #pragma unroll
        for (int wdx = 1; wdx < NTHREADS / 32; wdx++) v += s_warp[wdx];

        // Deterministic fixed-point accumulation
        long long fx = __double2ll_rn((double)v * FXSCALE);
        atomicAdd(&g_acc, (unsigned long long)fx);
        __threadfence();
        unsigned int ticket = atomicAdd(&g_count, 1u);
        if (ticket == NBLOCKS - 1) {
            long long total = (long long)atomicAdd(&g_acc, 0ULL);
            out[0] = (float)((double)total / FXSCALE
                             * (1.0 / (2.0 * (double)NB * (double)NP)));
            g_acc   = 0ULL;
            __threadfence();
            g_count = 0u;
        }
    }
}

extern "C" void kernel_launch(void* const* d_in, const int* in_sizes, int n_in,
                              void* d_out, int out_size) {
    const float* pred = (const float*)d_in[0];
    const float* tgt  = (const float*)d_in[1];
    const float* wgt  = (const float*)d_in[2];
    const float* pts  = (const float*)d_in[3];
    const float* sym  = (const float*)d_in[4];

    pm_setup<<<NB, NTHREADS>>>(pred, tgt, wgt, pts, sym);
    pm_main<<<NBLOCKS, NTHREADS>>>(pts, (float*)d_out);
}

// round 11
// speedup vs baseline: 1.1187x; 1.1187x over previous
#include <cuda_runtime.h>

// PMLoss: PoseCNN point-matching loss, single fused kernel with in-block
// heavy-first unit permutation (balances symmetric ROIs across SMs).

#define NB        128
#define NC        22
#define NP        1024
#define NPAIR     (NP / 2)
#define NCHUNK    8
#define NTHREADS  128                  // == NP / NCHUNK ; also == NB
#define NBLOCKS   (NB * NCHUNK)
#define BIGF      3.402823e38f

#define FXSCALE   1099511627776.0      // 2^40 fixed-point scale

__device__ unsigned long long g_acc;     // zero at load; last block resets
__device__ unsigned int       g_count;   // zero at load; last block resets

__device__ __forceinline__ unsigned long long pack2(float lo, float hi) {
    unsigned long long r;
    asm("mov.b64 %0, {%1, %2};" : "=l"(r) : "f"(lo), "f"(hi));
    return r;
}
__device__ __forceinline__ void unpack2(unsigned long long v, float& lo, float& hi) {
    asm("mov.b64 {%0, %1}, %2;" : "=f"(lo), "=f"(hi) : "l"(v));
}
// Packed dual fp32 FMA (FFMA2) — only reachable via PTX fma.rn.f32x2.
__device__ __forceinline__ unsigned long long fma2(
    unsigned long long a, unsigned long long b, unsigned long long c) {
    unsigned long long d;
    asm("fma.rn.f32x2 %0, %1, %2, %3;" : "=l"(d) : "l"(a), "l"(b), "l"(c));
    return d;
}

__device__ __forceinline__ float warp_reduce_sum(float v) {
    v += __shfl_xor_sync(0xffffffffu, v, 16);
    v += __shfl_xor_sync(0xffffffffu, v, 8);
    v += __shfl_xor_sync(0xffffffffu, v, 4);
    v += __shfl_xor_sync(0xffffffffu, v, 2);
    v += __shfl_xor_sync(0xffffffffu, v, 1);
    return v;
}

__device__ __forceinline__ int roi_argmax(const float* __restrict__ wgt, int r) {
    const float* w = wgt + r * 4 * NC;
    int cls = 0; float best = w[0];
    #pragma unroll
    for (int c = 1; c < NC; c++) {
        float v = w[4 * c];
        if (v > best) { best = v; cls = c; }
    }
    return cls;
}

__global__ __launch_bounds__(NTHREADS, 4) void pm_loss_main(
    const float* __restrict__ pred, const float* __restrict__ tgt,
    const float* __restrict__ wgt,  const float* __restrict__ points,
    const float* __restrict__ sym,  float* __restrict__ out)
{
    const int tid = threadIdx.x;

    __shared__ ulonglong2 s_xy[NPAIR];   // packed (-2x,-2y) pairs  (8 KB)
    __shared__ ulonglong2 s_zw[NPAIR];   // packed (-2z, n) pairs   (8 KB)
    __shared__ float s_R[18];            // Rp[0..8], Rt[9..17]
    __shared__ int   s_flag[NB];
    __shared__ int   s_pref[NB];
    __shared__ int   s_clsArr[NB];
    __shared__ int   s_b;
    __shared__ float s_warp[NTHREADS / 32];

    // ── Heavy-first unit permutation (every block, deterministic) ──
    // Thread t classifies ROI t  (NTHREADS == NB).
    {
        int c = roi_argmax(wgt, tid);
        s_clsArr[tid] = c;
        int f = (sym[c] > 0.f) ? 1 : 0;
        s_flag[tid] = f;
        s_pref[tid] = f;
    }
    __syncthreads();
    // Inclusive Hillis-Steele scan over 128 flags.
    #pragma unroll
    for (int off = 1; off < NB; off <<= 1) {
        int v   = s_pref[tid];
        int add = (tid >= off) ? s_pref[tid - off] : 0;
        __syncthreads();
        s_pref[tid] = v + add;
        __syncthreads();
    }
    const int H    = s_pref[NB - 1];            // number of heavy ROIs
    const int excl = s_pref[tid] - s_flag[tid]; // exclusive prefix for ROI tid
    {
        const int bid = blockIdx.x;
        if (bid < NCHUNK * H) {
            int j = bid >> 3;                               // heavy unit index
            if (s_flag[tid] && excl == j) s_b = tid;
        } else {
            int j = (bid - NCHUNK * H) >> 3;                // light unit index
            if (!s_flag[tid] && (tid - excl) == j) s_b = tid;
        }
    }
    __syncthreads();
    const int b     = s_b;
    const int chunk = blockIdx.x & (NCHUNK - 1);   // 8H is a multiple of 8
    const int heavy = s_flag[b];
    const int cls   = s_clsArr[b];

    // ── Per-ROI rotation matrices ──
    if (tid == 0) {
        const float* qp = pred + b * 4 * NC + 4 * cls;
        float qw = qp[0], qx = qp[1], qy = qp[2], qz = qp[3];
        float inv = rsqrtf(qw*qw + qx*qx + qy*qy + qz*qz);
        qw *= inv; qx *= inv; qy *= inv; qz *= inv;
        s_R[0] = 1.f - 2.f*(qy*qy + qz*qz); s_R[1] = 2.f*(qx*qy - qw*qz); s_R[2] = 2.f*(qx*qz + qw*qy);
        s_R[3] = 2.f*(qx*qy + qw*qz); s_R[4] = 1.f - 2.f*(qx*qx + qz*qz); s_R[5] = 2.f*(qy*qz - qw*qx);
        s_R[6] = 2.f*(qx*qz - qw*qy); s_R[7] = 2.f*(qy*qz + qw*qx); s_R[8] = 1.f - 2.f*(qx*qx + qy*qy);

        const float* qt = tgt + b * 4 * NC + 4 * cls;
        qw = qt[0]; qx = qt[1]; qy = qt[2]; qz = qt[3];
        s_R[ 9] = 1.f - 2.f*(qy*qy + qz*qz); s_R[10] = 2.f*(qx*qy - qw*qz); s_R[11] = 2.f*(qx*qz + qw*qy);
        s_R[12] = 2.f*(qx*qy + qw*qz); s_R[13] = 1.f - 2.f*(qx*qx + qz*qz); s_R[14] = 2.f*(qy*qz - qw*qx);
        s_R[15] = 2.f*(qx*qz - qw*qy); s_R[16] = 2.f*(qy*qz + qw*qx); s_R[17] = 1.f - 2.f*(qx*qx + qy*qy);
    }
    __syncthreads();

    const float* pts = points + (size_t)cls * NP * 3;

    // Own predicted-rotated point
    const int p = chunk * NTHREADS + tid;
    const float px = pts[3*p], py = pts[3*p + 1], pz = pts[3*p + 2];
    float ppx, ppy, ppz;
    {
        const float r0 = s_R[0], r1 = s_R[1], r2 = s_R[2];
        const float r3 = s_R[3], r4 = s_R[4], r5 = s_R[5];
        const float r6 = s_R[6], r7 = s_R[7], r8 = s_R[8];
        ppx = r0*px + r1*py + r2*pz;
        ppy = r3*px + r4*py + r5*pz;
        ppz = r6*px + r7*py + r8*pz;
    }
    const float cp = ppx*ppx + ppy*ppy + ppz*ppz;

    float acc;
    if (heavy) {
        // Build packed target-rotated table in smem.
        {
            const float r0 = s_R[ 9], r1 = s_R[10], r2 = s_R[11];
            const float r3 = s_R[12], r4 = s_R[13], r5 = s_R[14];
            const float r6 = s_R[15], r7 = s_R[16], r8 = s_R[17];
            for (int i = tid; i < NPAIR; i += NTHREADS) {
                int q0 = 2 * i;
                float x0 = pts[3*q0+0], y0 = pts[3*q0+1], z0 = pts[3*q0+2];
                float x1 = pts[3*q0+3], y1 = pts[3*q0+4], z1 = pts[3*q0+5];
                float tx0 = r0*x0 + r1*y0 + r2*z0, tx1 = r0*x1 + r1*y1 + r2*z1;
                float ty0 = r3*x0 + r4*y0 + r5*z0, ty1 = r3*x1 + r4*y1 + r5*z1;
                float tz0 = r6*x0 + r7*y0 + r8*z0, tz1 = r6*x1 + r7*y1 + r8*z1;
                float n0 = tx0*tx0 + ty0*ty0 + tz0*tz0;
                float n1 = tx1*tx1 + ty1*ty1 + tz1*tz1;
                ulonglong2 xy, zw;
                xy.x = pack2(-2.f*tx0, -2.f*tx1);
                xy.y = pack2(-2.f*ty0, -2.f*ty1);
                zw.x = pack2(-2.f*tz0, -2.f*tz1);
                zw.y = pack2(n0, n1);
                s_xy[i] = xy;
                s_zw[i] = zw;
            }
        }
        __syncthreads();

        // min_q |pp - pt_q|^2 = cp + min_q(n_q - 2 pp.pt_q)
        const unsigned long long px2 = pack2(ppx, ppx);
        const unsigned long long py2 = pack2(ppy, ppy);
        const unsigned long long pz2 = pack2(ppz, ppz);
        float m0 = BIGF, m1 = BIGF, m2 = BIGF, m3 = BIGF;
        float m4 = BIGF, m5 = BIGF, m6 = BIGF, m7 = BIGF;

        #pragma unroll 1
        for (int i = 0; i < NPAIR; i += 8) {
            ulonglong2 x0 = s_xy[i+0], z0 = s_zw[i+0];
            ulonglong2 x1 = s_xy[i+1], z1 = s_zw[i+1];
            ulonglong2 x2 = s_xy[i+2], z2 = s_zw[i+2];
            ulonglong2 x3 = s_xy[i+3], z3 = s_zw[i+3];
            ulonglong2 x4 = s_xy[i+4], z4 = s_zw[i+4];
            ulonglong2 x5 = s_xy[i+5], z5 = s_zw[i+5];
            ulonglong2 x6 = s_xy[i+6], z6 = s_zw[i+6];
            ulonglong2 x7 = s_xy[i+7], z7 = s_zw[i+7];

            unsigned long long v0 = fma2(pz2, z0.x, fma2(py2, x0.y, fma2(px2, x0.x, z0.y)));
            unsigned long long v1 = fma2(pz2, z1.x, fma2(py2, x1.y, fma2(px2, x1.x, z1.y)));
            unsigned long long v2 = fma2(pz2, z2.x, fma2(py2, x2.y, fma2(px2, x2.x, z2.y)));
            unsigned long long v3 = fma2(pz2, z3.x, fma2(py2, x3.y, fma2(px2, x3.x, z3.y)));
            unsigned long long v4 = fma2(pz2, z4.x, fma2(py2, x4.y, fma2(px2, x4.x, z4.y)));
            unsigned long long v5 = fma2(pz2, z5.x, fma2(py2, x5.y, fma2(px2, x5.x, z5.y)));
            unsigned long long v6 = fma2(pz2, z6.x, fma2(py2, x6.y, fma2(px2, x6.x, z6.y)));
            unsigned long long v7 = fma2(pz2, z7.x, fma2(py2, x7.y, fma2(px2, x7.x, z7.y)));

            float a, bf;
            unpack2(v0, a, bf); m0 = fminf(m0, a); m1 = fminf(m1, bf);
            unpack2(v1, a, bf); m2 = fminf(m2, a); m3 = fminf(m3, bf);
            unpack2(v2, a, bf); m4 = fminf(m4, a); m5 = fminf(m5, bf);
            unpack2(v3, a, bf); m6 = fminf(m6, a); m7 = fminf(m7, bf);
            unpack2(v4, a, bf); m0 = fminf(m0, a); m1 = fminf(m1, bf);
            unpack2(v5, a, bf); m2 = fminf(m2, a); m3 = fminf(m3, bf);
            unpack2(v6, a, bf); m4 = fminf(m4, a); m5 = fminf(m5, bf);
            unpack2(v7, a, bf); m6 = fminf(m6, a); m7 = fminf(m7, bf);
        }
        acc = cp + fminf(fminf(fminf(m0, m1), fminf(m2, m3)),
                         fminf(fminf(m4, m5), fminf(m6, m7)));
    } else {
        // Non-symmetric: rotate own point by Rt; |pp - pt|^2
        const float r0 = s_R[ 9], r1 = s_R[10], r2 = s_R[11];
        const float r3 = s_R[12], r4 = s_R[13], r5 = s_R[14];
        const float r6 = s_R[15], r7 = s_R[16], r8 = s_R[17];
        float tx = r0*px + r1*py + r2*pz;
        float ty = r3*px + r4*py + r5*pz;
        float tz = r6*px + r7*py + r8*pz;
        float dx = ppx - tx, dy = ppy - ty, dz = ppz - tz;
        acc = dx*dx + dy*dy + dz*dz;
        (void)cp;
    }

    // Block reduction
    float s = warp_reduce_sum(acc);
    if ((tid & 31) == 0) s_warp[tid >> 5] = s;
    __syncthreads();
    if (tid == 0) {
        float v = s_warp[0];
        #pragma unroll
        for (int wdx = 1; wdx < NTHREADS / 32; wdx++) v += s_warp[wdx];

        // Deterministic fixed-point accumulation
        long long fx = __double2ll_rn((double)v * FXSCALE);
        atomicAdd(&g_acc, (unsigned long long)fx);
        __threadfence();
        unsigned int ticket = atomicAdd(&g_count, 1u);
        if (ticket == NBLOCKS - 1) {
            long long total = (long long)atomicAdd(&g_acc, 0ULL);
            out[0] = (float)((double)total / FXSCALE
                             * (1.0 / (2.0 * (double)NB * (double)NP)));
            g_acc   = 0ULL;
            __threadfence();
            g_count = 0u;
        }
    }
}

extern "C" void kernel_launch(void* const* d_in, const int* in_sizes, int n_in,
                              void* d_out, int out_size) {
    const float* pred = (const float*)d_in[0];
    const float* tgt  = (const float*)d_in[1];
    const float* wgt  = (const float*)d_in[2];
    const float* pts  = (const float*)d_in[3];
    const float* sym  = (const float*)d_in[4];

    pm_loss_main<<<NBLOCKS, NTHREADS>>>(pred, tgt, wgt, pts, sym, (float*)d_out);
}

// round 15
// speedup vs baseline: 2.1235x; 1.8982x over previous
#include <cuda_runtime.h>

// PMLoss: PoseCNN point-matching loss, single fused kernel.
// Heavy (symmetric) blocks: 4 warps split the q-range (256 q each), each lane
// carries 4 p-points -> 4x fewer LDS, 2x shorter warps; smem min-combine.

#define NB        128
#define NC        22
#define NP        1024
#define NPAIR     (NP / 2)
#define NCHUNK    8
#define NTHREADS  128                  // 4 warps; heavy: 32 lanes x 4 p = 128 p
#define NBLOCKS   (NB * NCHUNK)
#define BIGF      3.402823e38f

#define FXSCALE   1099511627776.0      // 2^40 fixed-point scale

__device__ unsigned long long g_acc;     // zero at load; last block resets
__device__ unsigned int       g_count;   // zero at load; last block resets

__device__ __forceinline__ unsigned long long pack2(float lo, float hi) {
    unsigned long long r;
    asm("mov.b64 %0, {%1, %2};" : "=l"(r) : "f"(lo), "f"(hi));
    return r;
}
__device__ __forceinline__ void unpack2(unsigned long long v, float& lo, float& hi) {
    asm("mov.b64 {%0, %1}, %2;" : "=f"(lo), "=f"(hi) : "l"(v));
}
// Packed dual fp32 FMA (FFMA2) — only reachable via PTX fma.rn.f32x2.
__device__ __forceinline__ unsigned long long fma2(
    unsigned long long a, unsigned long long b, unsigned long long c) {
    unsigned long long d;
    asm("fma.rn.f32x2 %0, %1, %2, %3;" : "=l"(d) : "l"(a), "l"(b), "l"(c));
    return d;
}

__device__ __forceinline__ float warp_reduce_sum(float v) {
    v += __shfl_xor_sync(0xffffffffu, v, 16);
    v += __shfl_xor_sync(0xffffffffu, v, 8);
    v += __shfl_xor_sync(0xffffffffu, v, 4);
    v += __shfl_xor_sync(0xffffffffu, v, 2);
    v += __shfl_xor_sync(0xffffffffu, v, 1);
    return v;
}

__global__ __launch_bounds__(NTHREADS, 6) void pm_loss_main(
    const float* __restrict__ pred, const float* __restrict__ tgt,
    const float* __restrict__ wgt,  const float* __restrict__ points,
    const float* __restrict__ sym,  float* __restrict__ out)
{
    const int chunk = blockIdx.x;    // consecutive bids = chunks of same ROI
    const int b     = blockIdx.y;    // -> heavy ROI spreads across 8 SMs
    const int tid   = threadIdx.x;
    const int lane  = tid & 31;
    const int wrp   = tid >> 5;

    __shared__ ulonglong2 s_xy[NPAIR];        // packed (-2x,-2y)   (8 KB)
    __shared__ ulonglong2 s_zw[NPAIR];        // packed (-2z, n)    (8 KB)
    __shared__ float s_part[4][NTHREADS];     // per-warp partial mins (2 KB)
    __shared__ float s_cp[NTHREADS];          // |pp|^2 per p       (0.5 KB)
    __shared__ float s_R[18];                 // Rp[0..8], Rt[9..17]
    __shared__ int   s_cls;
    __shared__ float s_issym;
    __shared__ float s_warp[NTHREADS / 32];

    if (tid == 0) {
        // argmax over weight[b, c, 0] (first-max, matching jnp.argmax)
        const float* w = wgt + b * 4 * NC;
        int cls = 0; float best = w[0];
        #pragma unroll
        for (int c = 1; c < NC; c++) {
            float v = w[4 * c];
            if (v > best) { best = v; cls = c; }
        }
        s_cls   = cls;
        s_issym = sym[cls];

        // predicted quaternion (normalized) -> Rp
        const float* qp = pred + b * 4 * NC + 4 * cls;
        float qw = qp[0], qx = qp[1], qy = qp[2], qz = qp[3];
        float inv = rsqrtf(qw*qw + qx*qx + qy*qy + qz*qz);
        qw *= inv; qx *= inv; qy *= inv; qz *= inv;
        s_R[0] = 1.f - 2.f*(qy*qy + qz*qz); s_R[1] = 2.f*(qx*qy - qw*qz); s_R[2] = 2.f*(qx*qz + qw*qy);
        s_R[3] = 2.f*(qx*qy + qw*qz); s_R[4] = 1.f - 2.f*(qx*qx + qz*qz); s_R[5] = 2.f*(qy*qz - qw*qx);
        s_R[6] = 2.f*(qx*qz - qw*qy); s_R[7] = 2.f*(qy*qz + qw*qx); s_R[8] = 1.f - 2.f*(qx*qx + qy*qy);

        // target quaternion (already unit-norm) -> Rt
        const float* qt = tgt + b * 4 * NC + 4 * cls;
        qw = qt[0]; qx = qt[1]; qy = qt[2]; qz = qt[3];
        s_R[ 9] = 1.f - 2.f*(qy*qy + qz*qz); s_R[10] = 2.f*(qx*qy - qw*qz); s_R[11] = 2.f*(qx*qz + qw*qy);
        s_R[12] = 2.f*(qx*qy + qw*qz); s_R[13] = 1.f - 2.f*(qx*qx + qz*qz); s_R[14] = 2.f*(qy*qz - qw*qx);
        s_R[15] = 2.f*(qx*qz - qw*qy); s_R[16] = 2.f*(qy*qz + qw*qx); s_R[17] = 1.f - 2.f*(qx*qx + qy*qy);
    }
    __syncthreads();

    const int  cls  = s_cls;
    const bool symb = (s_issym > 0.f);       // block-uniform
    const float* pts = points + (size_t)cls * NP * 3;
    const int pbase = chunk * NTHREADS;

    float acc;   // defined for tid's own p below

    if (symb) {
        // ── Build packed target-rotated table (all 1024 q) ──
        {
            const float r0 = s_R[ 9], r1 = s_R[10], r2 = s_R[11];
            const float r3 = s_R[12], r4 = s_R[13], r5 = s_R[14];
            const float r6 = s_R[15], r7 = s_R[16], r8 = s_R[17];
            for (int i = tid; i < NPAIR; i += NTHREADS) {
                int q0 = 2 * i;
                float x0 = pts[3*q0+0], y0 = pts[3*q0+1], z0 = pts[3*q0+2];
                float x1 = pts[3*q0+3], y1 = pts[3*q0+4], z1 = pts[3*q0+5];
                float tx0 = r0*x0 + r1*y0 + r2*z0, tx1 = r0*x1 + r1*y1 + r2*z1;
                float ty0 = r3*x0 + r4*y0 + r5*z0, ty1 = r3*x1 + r4*y1 + r5*z1;
                float tz0 = r6*x0 + r7*y0 + r8*z0, tz1 = r6*x1 + r7*y1 + r8*z1;
                float n0 = tx0*tx0 + ty0*ty0 + tz0*tz0;
                float n1 = tx1*tx1 + ty1*ty1 + tz1*tz1;
                ulonglong2 xy, zw;
                xy.x = pack2(-2.f*tx0, -2.f*tx1);
                xy.y = pack2(-2.f*ty0, -2.f*ty1);
                zw.x = pack2(-2.f*tz0, -2.f*tz1);
                zw.y = pack2(n0, n1);
                s_xy[i] = xy;
                s_zw[i] = zw;
            }
        }

        // ── Each lane owns 4 p's: p_j = pbase + lane + 32*j ──
        unsigned long long px2[4], py2[4], pz2[4];
        float cpj[4];
        {
            const float r0 = s_R[0], r1 = s_R[1], r2 = s_R[2];
            const float r3 = s_R[3], r4 = s_R[4], r5 = s_R[5];
            const float r6 = s_R[6], r7 = s_R[7], r8 = s_R[8];
            #pragma unroll
            for (int j = 0; j < 4; j++) {
                int p = pbase + lane + 32 * j;
                float x = pts[3*p], y = pts[3*p+1], z = pts[3*p+2];
                float ppx = r0*x + r1*y + r2*z;
                float ppy = r3*x + r4*y + r5*z;
                float ppz = r6*x + r7*y + r8*z;
                px2[j] = pack2(ppx, ppx);
                py2[j] = pack2(ppy, ppy);
                pz2[j] = pack2(ppz, ppz);
                cpj[j] = ppx*ppx + ppy*ppy + ppz*ppz;
                if (wrp == 0) s_cp[lane + 32 * j] = cpj[j];
            }
        }
        __syncthreads();

        // ── Warp w scans pairs [w*128, w*128+128) for its 128 p's ──
        float m0 = BIGF, m1 = BIGF, m2 = BIGF, m3 = BIGF;
        const int i0 = wrp * (NPAIR / 4);
        #pragma unroll 1
        for (int i = i0; i < i0 + NPAIR / 4; i += 2) {
            ulonglong2 xyA = s_xy[i],   zwA = s_zw[i];
            ulonglong2 xyB = s_xy[i+1], zwB = s_zw[i+1];

            unsigned long long vA0 = fma2(pz2[0], zwA.x, fma2(py2[0], xyA.y, fma2(px2[0], xyA.x, zwA.y)));
            unsigned long long vA1 = fma2(pz2[1], zwA.x, fma2(py2[1], xyA.y, fma2(px2[1], xyA.x, zwA.y)));
            unsigned long long vA2 = fma2(pz2[2], zwA.x, fma2(py2[2], xyA.y, fma2(px2[2], xyA.x, zwA.y)));
            unsigned long long vA3 = fma2(pz2[3], zwA.x, fma2(py2[3], xyA.y, fma2(px2[3], xyA.x, zwA.y)));
            unsigned long long vB0 = fma2(pz2[0], zwB.x, fma2(py2[0], xyB.y, fma2(px2[0], xyB.x, zwB.y)));
            unsigned long long vB1 = fma2(pz2[1], zwB.x, fma2(py2[1], xyB.y, fma2(px2[1], xyB.x, zwB.y)));
            unsigned long long vB2 = fma2(pz2[2], zwB.x, fma2(py2[2], xyB.y, fma2(px2[2], xyB.x, zwB.y)));
            unsigned long long vB3 = fma2(pz2[3], zwB.x, fma2(py2[3], xyB.y, fma2(px2[3], xyB.x, zwB.y)));

            float a, bf;
            unpack2(vA0, a, bf); m0 = fminf(m0, fminf(a, bf));
            unpack2(vA1, a, bf); m1 = fminf(m1, fminf(a, bf));
            unpack2(vA2, a, bf); m2 = fminf(m2, fminf(a, bf));
            unpack2(vA3, a, bf); m3 = fminf(m3, fminf(a, bf));
            unpack2(vB0, a, bf); m0 = fminf(m0, fminf(a, bf));
            unpack2(vB1, a, bf); m1 = fminf(m1, fminf(a, bf));
            unpack2(vB2, a, bf); m2 = fminf(m2, fminf(a, bf));
            unpack2(vB3, a, bf); m3 = fminf(m3, fminf(a, bf));
        }
        s_part[wrp][lane +  0] = m0;
        s_part[wrp][lane + 32] = m1;
        s_part[wrp][lane + 64] = m2;
        s_part[wrp][lane + 96] = m3;
        __syncthreads();

        // ── Combine: thread tid owns p-index tid ──
        float mn = fminf(fminf(s_part[0][tid], s_part[1][tid]),
                         fminf(s_part[2][tid], s_part[3][tid]));
        acc = s_cp[tid] + mn;
    } else {
        // Non-symmetric: thread tid owns p = pbase + tid; |pp - pt|^2
        const int p = pbase + tid;
        const float x = pts[3*p], y = pts[3*p+1], z = pts[3*p+2];
        const float a0 = s_R[0], a1 = s_R[1], a2 = s_R[2];
        const float a3 = s_R[3], a4 = s_R[4], a5 = s_R[5];
        const float a6 = s_R[6], a7 = s_R[7], a8 = s_R[8];
        const float t0 = s_R[ 9], t1 = s_R[10], t2 = s_R[11];
        const float t3 = s_R[12], t4 = s_R[13], t5 = s_R[14];
        const float t6 = s_R[15], t7 = s_R[16], t8 = s_R[17];
        float ppx = a0*x + a1*y + a2*z;
        float ppy = a3*x + a4*y + a5*z;
        float ppz = a6*x + a7*y + a8*z;
        float tx  = t0*x + t1*y + t2*z;
        float ty  = t3*x + t4*y + t5*z;
        float tz  = t6*x + t7*y + t8*z;
        float dx = ppx - tx, dy = ppy - ty, dz = ppz - tz;
        acc = dx*dx + dy*dy + dz*dz;
    }

    // Block reduction
    float s = warp_reduce_sum(acc);
    if ((tid & 31) == 0) s_warp[tid >> 5] = s;
    __syncthreads();
    if (tid == 0) {
        float v = s_warp[0];
        #pragma unroll
        for (int wdx = 1; wdx < NTHREADS / 32; wdx++) v += s_warp[wdx];

        // Deterministic fixed-point accumulation
        long long fx = __double2ll_rn((double)v * FXSCALE);
        atomicAdd(&g_acc, (unsigned long long)fx);
        __threadfence();
        unsigned int ticket = atomicAdd(&g_count, 1u);
        if (ticket == NBLOCKS - 1) {
            long long total = (long long)atomicAdd(&g_acc, 0ULL);
            out[0] = (float)((double)total / FXSCALE
                             * (1.0 / (2.0 * (double)NB * (double)NP)));
            g_acc   = 0ULL;
            __threadfence();
            g_count = 0u;
        }
    }
}

extern "C" void kernel_launch(void* const* d_in, const int* in_sizes, int n_in,
                              void* d_out, int out_size) {
    const float* pred = (const float*)d_in[0];
    const float* tgt  = (const float*)d_in[1];
    const float* wgt  = (const float*)d_in[2];
    const float* pts  = (const float*)d_in[3];
    const float* sym  = (const float*)d_in[4];

    dim3 grid(NCHUNK, NB);
    pm_loss_main<<<grid, NTHREADS>>>(pred, tgt, wgt, pts, sym, (float*)d_out);
}